// round 2
// baseline (speedup 1.0000x reference)
#include <cuda_runtime.h>
#include <cstddef>

// ============================================================================
// MotionGenerator: fused masked-conv1d(stride2,reflect pad7,K15) + pool + leakyrelu
//
// Structure (hardcoded from the reference's constant EDGES/mask/pool_w):
//   21 joints, 64 in-ch/joint, 128 out-ch/joint, 12 pool groups x 128 ch.
//   85 nonzero (group, joint) blocks out of 12*21.
//
// Pass 1 (prep): fold mask + pooling into compact weights
//   Wc[slot][k][ci][oc]  (slot = (group, jj) pair, 85 slots)
// Pass 2 (main): block-sparse implicit GEMM, tile = 128 oc x 128 t per block.
//   x window per joint cached in smem, split by parity so each tap k is a
//   unit-stride shifted window (stride-2 conv trick).
// ============================================================================

#define NG 12
#define NSLOT 85
#define XPITCH 136          // parity-array row pitch (floats)
#define SMEM_FLOATS (64*XPITCH*2 + 64*128)   // xe + xo + Ws = 25600 floats = 100 KB

__constant__ int   cOff[NG + 1] = {0, 8, 19, 26, 35, 39, 48, 52, 61, 65, 74, 78, 85};
__constant__ int   cE0[NG] = {0, 1, 3, 4, 6, 8, 10, 12, 14, 16, 18, 20};
__constant__ int   cE1[NG] = {-1, 2, -1, 5, 7, 9, 11, 13, 15, 17, 19, -1};

__constant__ int cSlotG[NSLOT] = {
    0,0,0,0,0,0,0,0,
    1,1,1,1,1,1,1,1,1,1,1,
    2,2,2,2,2,2,2,
    3,3,3,3,3,3,3,3,3,
    4,4,4,4,
    5,5,5,5,5,5,5,5,5,
    6,6,6,6,
    7,7,7,7,7,7,7,7,7,
    8,8,8,8,
    9,9,9,9,9,9,9,9,9,
    10,10,10,10,
    11,11,11,11,11,11,11
};

__constant__ int cJ[NSLOT] = {
    0,1,2,12,13,16,17,20,                    // g0  [e0]
    0,1,2,3,4,5,8,9,12,16,20,                // g1  [e1,e2]
    1,2,3,4,5,8,9,                           // g2  [e3]
    1,2,3,4,5,6,7,8,9,                       // g3  [e4,e5]
    4,5,6,7,                                 // g4  [e6,e7]
    1,2,3,4,5,8,9,10,11,                     // g5  [e8,e9]
    8,9,10,11,                               // g6  [e10,e11]
    0,1,12,13,14,15,16,17,20,                // g7  [e12,e13]
    12,13,14,15,                             // g8  [e14,e15]
    0,1,12,13,16,17,18,19,20,                // g9  [e16,e17]
    16,17,18,19,                             // g10 [e18,e19]
    0,1,2,12,13,16,17                        // g11 [global row 20]
};

__constant__ float cC0[NSLOT] = {
    1,1,1,1,1,1,1,1,
    0.5f,0.5f,0.5f,0.5f,0.5f,0.0f,0.5f,0.0f,0.5f,0.5f,0.5f,
    1,1,1,1,1,1,1,
    0.5f,0.5f,0.5f,0.5f,0.5f,0.5f,0.0f,0.5f,0.5f,
    0.5f,0.5f,0.5f,0.5f,
    0.5f,0.5f,0.5f,0.5f,0.5f,0.5f,0.5f,0.5f,0.0f,
    0.5f,0.5f,0.5f,0.5f,
    0.5f,0.5f,0.5f,0.5f,0.5f,0.0f,0.5f,0.5f,0.5f,
    0.5f,0.5f,0.5f,0.5f,
    0.5f,0.5f,0.5f,0.5f,0.5f,0.5f,0.5f,0.0f,0.5f,
    0.5f,0.5f,0.5f,0.5f,
    1,1,1,1,1,1,1
};

__constant__ float cC1[NSLOT] = {
    0,0,0,0,0,0,0,0,
    0.5f,0.5f,0.5f,0.5f,0.5f,0.5f,0.5f,0.5f,0.0f,0.0f,0.5f,
    0,0,0,0,0,0,0,
    0.0f,0.5f,0.5f,0.5f,0.5f,0.5f,0.5f,0.5f,0.0f,
    0.0f,0.5f,0.5f,0.5f,
    0.0f,0.5f,0.5f,0.5f,0.0f,0.5f,0.5f,0.5f,0.5f,
    0.0f,0.5f,0.5f,0.5f,
    0.5f,0.0f,0.5f,0.5f,0.5f,0.5f,0.5f,0.0f,0.5f,
    0.0f,0.5f,0.5f,0.5f,
    0.5f,0.0f,0.5f,0.0f,0.5f,0.5f,0.5f,0.5f,0.5f,   // g9: j=20 coef FIXED 0.0 -> 0.5
    0.0f,0.5f,0.5f,0.5f,
    0,0,0,0,0,0,0
};

// Compacted folded weights: [85 slots][15 taps][64 ci][128 oc] = 41.8 MB
__device__ __align__(16) float g_Wc[(size_t)NSLOT * 15 * 64 * 128];

// ----------------------------------------------------------------------------
// Prep: Wc[s][k][ci][oc] = c0*weight[e0*128+oc, j*64+ci, k] + c1*weight[e1...]
// weight layout: [2688][1344][15] row-major -> row stride 20160
// ----------------------------------------------------------------------------
__global__ void prep_wc(const float* __restrict__ weight) {
    const int s  = blockIdx.x;   // 0..84
    const int oc = blockIdx.y;   // 0..127
    const int g  = cSlotG[s];
    const int j  = cJ[s];
    const float c0 = cC0[s], c1 = cC1[s];
    const int e0 = cE0[g], e1 = cE1[g];

    const float* __restrict__ w0 = weight + (size_t)(e0 * 128 + oc) * 20160 + (size_t)j * 960;
    const float* __restrict__ w1 = (e1 >= 0)
        ? weight + (size_t)(e1 * 128 + oc) * 20160 + (size_t)j * 960 : nullptr;

    for (int q = threadIdx.x; q < 960; q += blockDim.x) {
        float v = c0 * w0[q];
        if (w1) v += c1 * w1[q];
        const int ci = q / 15;
        const int k  = q - ci * 15;
        g_Wc[(((size_t)s * 15 + k) * 64 + ci) * 128 + oc] = v;
    }
}

// ----------------------------------------------------------------------------
// Main: block = (group g, t-tile, batch). Tile 128 oc x 128 t, 256 threads,
// each thread 8 oc x 8 t (t strided by 16 -> conflict-free smem reads).
// ----------------------------------------------------------------------------
__global__ __launch_bounds__(256, 2)
void motion_main(const float* __restrict__ x,
                 const float* __restrict__ bias,
                 float* __restrict__ out) {
    extern __shared__ float sm[];
    float* xe = sm;                      // [64][XPITCH]  even positions
    float* xo = sm + 64 * XPITCH;        // [64][XPITCH]  odd positions
    float* Ws = sm + 2 * 64 * XPITCH;    // [64 ci][128 oc]

    const int g    = blockIdx.x;    // 0..11
    const int tile = blockIdx.y;    // 0..15
    const int b    = blockIdx.z;    // 0..7
    const int tid  = threadIdx.x;
    const int ty   = tid >> 4;      // 0..15 -> oc block
    const int tx   = tid & 15;      // 0..15 -> t lane
    const int warp = tid >> 5, lane = tid & 31;

    const int t0   = tile << 7;
    const int base = 2 * t0 - 7;    // leftmost (unreflected) x position of window

    float acc[8][8];
#pragma unroll
    for (int i = 0; i < 8; ++i)
#pragma unroll
        for (int u = 0; u < 8; ++u) acc[i][u] = 0.f;

    const int off0 = cOff[g];
    const int nj   = cOff[g + 1] - off0;

    for (int jj = 0; jj < nj; ++jj) {
        const int s = off0 + jj;
        const int j = cJ[s];

        __syncthreads();   // previous iteration's compute must be done (xe/xo/Ws reuse)

        // ---- load x window for joint j: 64 ch x 269 positions, parity split ----
        const float* __restrict__ xj = x + ((size_t)b * 1344 + (size_t)j * 64) * 4096;
        for (int ci = warp; ci < 64; ci += 8) {
            const float* __restrict__ src = xj + (size_t)ci * 4096;
            for (int r = lane; r < 269; r += 32) {
                int pos = base + r;
                pos = pos < 0 ? -pos : pos;
                pos = pos > 4095 ? 8190 - pos : pos;   // reflect
                const float v = src[pos];
                if (r & 1) xo[ci * XPITCH + (r >> 1)] = v;
                else       xe[ci * XPITCH + (r >> 1)] = v;
            }
        }

        const float4* __restrict__ wsrc_base =
            reinterpret_cast<const float4*>(g_Wc) + (size_t)s * 15 * 2048;

        for (int k = 0; k < 15; ++k) {
            __syncthreads();   // prior compute done before overwriting Ws
            // ---- stage Wc[s][k] chunk: 64 ci x 128 oc ----
            const float4* __restrict__ wsrc = wsrc_base + (size_t)k * 2048;
            float4* wdst = reinterpret_cast<float4*>(Ws);
#pragma unroll
            for (int i = 0; i < 8; ++i) wdst[tid + (i << 8)] = wsrc[tid + (i << 8)];
            __syncthreads();

            // tap k reads parity array (k odd -> xo, k even -> xe) at shift k>>1
            const float* __restrict__ xrow = ((k & 1) ? xo : xe) + tx + (k >> 1);
            const float* __restrict__ wrow = Ws + (ty << 3);

#pragma unroll 2
            for (int ci = 0; ci < 64; ++ci) {
                const float4 a0 = *reinterpret_cast<const float4*>(wrow + ci * 128);
                const float4 a1 = *reinterpret_cast<const float4*>(wrow + ci * 128 + 4);
                float xb[8];
#pragma unroll
                for (int u = 0; u < 8; ++u) xb[u] = xrow[ci * XPITCH + (u << 4)];
                const float a[8] = {a0.x, a0.y, a0.z, a0.w, a1.x, a1.y, a1.z, a1.w};
#pragma unroll
                for (int i = 0; i < 8; ++i)
#pragma unroll
                    for (int u = 0; u < 8; ++u)
                        acc[i][u] = fmaf(a[i], xb[u], acc[i][u]);
            }
        }
    }

    // ---- epilogue: pooled bias + leaky relu(0.2), write out[b][g*128+oc][t] ----
    const int e0 = cE0[g], e1 = cE1[g];
    const float sc = (e1 >= 0) ? 0.5f : 1.0f;
    float* __restrict__ orow =
        out + ((size_t)b * 1536 + (size_t)(g << 7) + (size_t)(ty << 3)) * 2048 + t0 + tx;
#pragma unroll
    for (int i = 0; i < 8; ++i) {
        const int oc = (ty << 3) + i;
        float bv = bias[e0 * 128 + oc];
        if (e1 >= 0) bv += bias[e1 * 128 + oc];
        bv *= sc;
#pragma unroll
        for (int u = 0; u < 8; ++u) {
            float v = acc[i][u] + bv;
            v = v > 0.f ? v : 0.2f * v;
            orow[(size_t)i * 2048 + (u << 4)] = v;
        }
    }
}

// ----------------------------------------------------------------------------
extern "C" void kernel_launch(void* const* d_in, const int* in_sizes, int n_in,
                              void* d_out, int out_size) {
    (void)in_sizes; (void)n_in; (void)out_size;
    const float* x      = (const float*)d_in[0];   // [8][1344][4096]
    const float* weight = (const float*)d_in[1];   // [2688][1344][15]
    const float* bias   = (const float*)d_in[2];   // [2688]
    float* out          = (float*)d_out;           // [8][1536][2048]

    cudaFuncSetAttribute(motion_main, cudaFuncAttributeMaxDynamicSharedMemorySize,
                         SMEM_FLOATS * (int)sizeof(float));

    dim3 gp(NSLOT, 128);
    prep_wc<<<gp, 256>>>(weight);

    dim3 gm(NG, 16, 8);
    motion_main<<<gm, 256, SMEM_FLOATS * sizeof(float)>>>(x, bias, out);
}